// round 11
// baseline (speedup 1.0000x reference)
#include <cuda_runtime.h>
#include <cuda_fp16.h>

#define NU 8
#define MA 1024
#define NPAIRS 28              // NU*(NU-1)/2
#define JC 32                  // j chunks per unit
#define JT 32                  // j tile size
#define THREADS 256
#define PAIR_BLOCKS (NPAIRS * JC)        // 896: full 1024 i (4/thread) x 32 j
#define TOTAL_BLOCKS (PAIR_BLOCKS + NU)  // +8 L1 blocks

__device__ float g_acc;        // single accumulator; reset by finalizer
__device__ unsigned g_ticket;  // arrival counter; reset by finalizer

__device__ __forceinline__ unsigned long long pk2(float a, float b) {
    unsigned long long r;
    asm("mov.b64 %0, {%1, %2};" : "=l"(r) : "f"(a), "f"(b));
    return r;
}
__device__ __forceinline__ void upk2(float& a, float& b, unsigned long long v) {
    asm("mov.b64 {%0, %1}, %2;" : "=f"(a), "=f"(b) : "l"(v));
}
__device__ __forceinline__ unsigned long long fma2(unsigned long long a, unsigned long long b, unsigned long long c) {
    unsigned long long d;
    asm("fma.rn.f32x2 %0, %1, %2, %3;" : "=l"(d) : "l"(a), "l"(b), "l"(c));
    return d;
}
__device__ __forceinline__ unsigned long long add2(unsigned long long a, unsigned long long b) {
    unsigned long long d;
    asm("add.rn.f32x2 %0, %1, %2;" : "=l"(d) : "l"(a), "l"(b));
    return d;
}

// Build rotation matrices + positions into shared (threads 0..7, one unit each)
__device__ __forceinline__ void build_R(float (*Rsh)[12],
                                        const float* __restrict__ pos,
                                        const float* __restrict__ euler,
                                        int tid) {
    if (tid < NU) {
        float phi = euler[tid * 3 + 0];
        float the = euler[tid * 3 + 1];
        float psi = euler[tid * 3 + 2];
        float cp = __cosf(phi), sp = __sinf(phi);
        float ct = __cosf(the), st = __sinf(the);
        float cs = __cosf(psi), ss = __sinf(psi);
        // R = Rz(psi) @ Ry(theta) @ Rx(phi)
        Rsh[tid][0] = cs * ct;
        Rsh[tid][1] = -ss * cp + cs * st * sp;
        Rsh[tid][2] = ss * sp + cs * st * cp;
        Rsh[tid][3] = ss * ct;
        Rsh[tid][4] = cs * cp + ss * st * sp;
        Rsh[tid][5] = -cs * sp + ss * st * cp;
        Rsh[tid][6] = -st;
        Rsh[tid][7] = ct * sp;
        Rsh[tid][8] = ct * cp;
        Rsh[tid][9]  = pos[tid * 3 + 0];
        Rsh[tid][10] = pos[tid * 3 + 1];
        Rsh[tid][11] = pos[tid * 3 + 2];
    }
}

// Transform atom m (coords in SMEM) with unit u's rotation+position
__device__ __forceinline__ void xform_s(const float (*Rsh)[12],
                                        const float* __restrict__ sc,
                                        int u, int m,
                                        float& px, float& py, float& pz, float& sq) {
    float cx = sc[m * 3 + 0];
    float cy = sc[m * 3 + 1];
    float cz = sc[m * 3 + 2];
    const float* R = Rsh[u];
    px = fmaf(R[0], cx, fmaf(R[1], cy, fmaf(R[2], cz, R[9])));
    py = fmaf(R[3], cx, fmaf(R[4], cy, fmaf(R[5], cz, R[10])));
    pz = fmaf(R[6], cx, fmaf(R[7], cy, fmaf(R[8], cz, R[11])));
    sq = px * px + py * py + pz * pz;
}

// ---------------------------------------------------------------------------
// Single fused kernel, 256-thread blocks, recompute prologue, f16x2 exp path.
// Blocks [0, 896): pair tiles: full 1024 i (4/thread) x 32 j.
// Blocks [896, 904): L1 per unit (+ L_com in the first one).
// arg = c_i + c_j + dot(Pi', Pj') = log2e*(1 - d2) <= log2e  (f16-safe)
// pen = exp2(arg); computed as h2exp2 on f16x2 pairs, accumulated with hadd2.
// ---------------------------------------------------------------------------
__global__ void __launch_bounds__(THREADS) fused_kernel(const float* __restrict__ pos,
                                                        const float* __restrict__ euler,
                                                        const float* __restrict__ coords,
                                                        float* __restrict__ out) {
    __shared__ float Rsh[NU][12];
    __shared__ __align__(16) float scoord[MA * 3];   // 12KB staged coords
    __shared__ __align__(16) float sj[4][JT];        // SoA j tile: X, Y, Z, c
    __shared__ float wsum[THREADS / 32];

    const float LOG2E = 1.4426950408889634f;
    const float S = 1.6986436005760381f;             // sqrt(2*log2e)
    int tid = threadIdx.x;
    int b = blockIdx.x;

    // Stage coords (768 float4 = 3072 floats) + build rotations
    {
        const float4* c4 = reinterpret_cast<const float4*>(coords);
        float4* s4 = reinterpret_cast<float4*>(scoord);
#pragma unroll
        for (int k = 0; k < 3; k++)
            s4[tid + k * THREADS] = c4[tid + k * THREADS];
    }
    build_R(Rsh, pos, euler, tid);
    __syncthreads();

    float blockContrib = 0.0f;   // value thread 0 will atomicAdd

    if (b < PAIR_BLOCKS) {
        int p  = b >> 5;          // pair index
        int jc = b & 31;          // j chunk
        // pair index -> (u, v), u < v
        int rem = p, u = 0, row = NU - 1;
        while (rem >= row) { rem -= row; row--; u++; }
        int v = u + 1 + rem;

        // Stage j tile (unit v)
        if (tid < JT) {
            float px, py, pz, sq;
            xform_s(Rsh, scoord, v, jc * JT + tid, px, py, pz, sq);
            sj[0][tid] = S * px;
            sj[1][tid] = S * py;
            sj[2][tid] = S * pz;
            sj[3][tid] = LOG2E * (0.5f - sq);
        }

        // i points (unit u): 4 per thread
        float px0, py0, pz0, sq0, px1, py1, pz1, sq1;
        float px2, py2, pz2, sq2, px3, py3, pz3, sq3;
        xform_s(Rsh, scoord, u, tid,                px0, py0, pz0, sq0);
        xform_s(Rsh, scoord, u, tid + THREADS,      px1, py1, pz1, sq1);
        xform_s(Rsh, scoord, u, tid + 2 * THREADS,  px2, py2, pz2, sq2);
        xform_s(Rsh, scoord, u, tid + 3 * THREADS,  px3, py3, pz3, sq3);

        unsigned long long DX0 = pk2(S * px0, S * px0), DY0 = pk2(S * py0, S * py0), DZ0 = pk2(S * pz0, S * pz0);
        unsigned long long DX1 = pk2(S * px1, S * px1), DY1 = pk2(S * py1, S * py1), DZ1 = pk2(S * pz1, S * pz1);
        unsigned long long DX2 = pk2(S * px2, S * px2), DY2 = pk2(S * py2, S * py2), DZ2 = pk2(S * pz2, S * pz2);
        unsigned long long DX3 = pk2(S * px3, S * px3), DY3 = pk2(S * py3, S * py3), DZ3 = pk2(S * pz3, S * pz3);
        float c0 = LOG2E * (0.5f - sq0), c1 = LOG2E * (0.5f - sq1);
        float c2 = LOG2E * (0.5f - sq2), c3 = LOG2E * (0.5f - sq3);
        unsigned long long CI0 = pk2(c0, c0), CI1 = pk2(c1, c1);
        unsigned long long CI2 = pk2(c2, c2), CI3 = pk2(c3, c3);

        __syncthreads();

        const unsigned long long* xp = reinterpret_cast<const unsigned long long*>(sj[0]);
        const unsigned long long* yp = reinterpret_cast<const unsigned long long*>(sj[1]);
        const unsigned long long* zp = reinterpret_cast<const unsigned long long*>(sj[2]);
        const unsigned long long* cp = reinterpret_cast<const unsigned long long*>(sj[3]);

        __half2 acc0 = __float2half2_rn(0.0f);
        __half2 acc1 = __float2half2_rn(0.0f);
        __half2 acc2 = __float2half2_rn(0.0f);
        __half2 acc3 = __float2half2_rn(0.0f);

#pragma unroll
        for (int t = 0; t < JT / 2; t++) {
            unsigned long long XJ = xp[t];
            unsigned long long YJ = yp[t];
            unsigned long long ZJ = zp[t];
            unsigned long long CJ = cp[t];
            float lo, hi;

            unsigned long long t0 = add2(CJ, CI0);
            t0 = fma2(DX0, XJ, t0);
            t0 = fma2(DY0, YJ, t0);
            t0 = fma2(DZ0, ZJ, t0);
            upk2(lo, hi, t0);
            acc0 = __hadd2(acc0, h2exp2(__floats2half2_rn(lo, hi)));

            unsigned long long t1 = add2(CJ, CI1);
            t1 = fma2(DX1, XJ, t1);
            t1 = fma2(DY1, YJ, t1);
            t1 = fma2(DZ1, ZJ, t1);
            upk2(lo, hi, t1);
            acc1 = __hadd2(acc1, h2exp2(__floats2half2_rn(lo, hi)));

            unsigned long long t2 = add2(CJ, CI2);
            t2 = fma2(DX2, XJ, t2);
            t2 = fma2(DY2, YJ, t2);
            t2 = fma2(DZ2, ZJ, t2);
            upk2(lo, hi, t2);
            acc2 = __hadd2(acc2, h2exp2(__floats2half2_rn(lo, hi)));

            unsigned long long t3 = add2(CJ, CI3);
            t3 = fma2(DX3, XJ, t3);
            t3 = fma2(DY3, YJ, t3);
            t3 = fma2(DZ3, ZJ, t3);
            upk2(lo, hi, t3);
            acc3 = __hadd2(acc3, h2exp2(__floats2half2_rn(lo, hi)));
        }

        float2 f0 = __half22float2(acc0);
        float2 f1 = __half22float2(acc1);
        float2 f2 = __half22float2(acc2);
        float2 f3 = __half22float2(acc3);
        float s = ((f0.x + f0.y) + (f1.x + f1.y)) + ((f2.x + f2.y) + (f3.x + f3.y));

#pragma unroll
        for (int o = 16; o > 0; o >>= 1)
            s += __shfl_xor_sync(0xFFFFFFFFu, s, o);
        if ((tid & 31) == 0) wsum[tid >> 5] = s;
        __syncthreads();
        if (tid == 0) {
            float bs = 0.f;
#pragma unroll
            for (int w = 0; w < THREADS / 32; w++) bs += wsum[w];
            blockContrib = 0.5f * bs;      // LAMBDA1 = 0.5
        }
    } else {
        // L1 block for unit u (+ L_com in the u==0 block)
        int u = b - PAIR_BLOCKS;
        float l1 = 0.0f;
#pragma unroll
        for (int k = 0; k < MA / THREADS; k++) {
            float px, py, pz, sq;
            xform_s(Rsh, scoord, u, k * THREADS + tid, px, py, pz, sq);
            l1 += sq;
        }
#pragma unroll
        for (int o = 16; o > 0; o >>= 1)
            l1 += __shfl_xor_sync(0xFFFFFFFFu, l1, o);
        if ((tid & 31) == 0) wsum[tid >> 5] = l1;
        __syncthreads();
        if (tid == 0) {
            float bs = 0.f;
#pragma unroll
            for (int w = 0; w < THREADS / 32; w++) bs += wsum[w];
            blockContrib = bs / (float)NU;      // contribution to L1 mean
            if (u == 0) {
                float ccx = 0.f, ccy = 0.f, ccz = 0.f;
#pragma unroll
                for (int uu = 0; uu < NU; uu++) {
                    ccx += Rsh[uu][9]; ccy += Rsh[uu][10]; ccz += Rsh[uu][11];
                }
                blockContrib += ccx * ccx + ccy * ccy + ccz * ccz;   // ALPHA = 1
            }
        }
    }

    // Accumulate + ticket finalize (thread 0 of every block)
    if (tid == 0) {
        atomicAdd(&g_acc, blockContrib);
        __threadfence();
        unsigned old = atomicAdd(&g_ticket, 1u);
        if (old == TOTAL_BLOCKS - 1) {
            __threadfence();
            float total = *((volatile float*)&g_acc);
            out[0] = total;
            g_acc = 0.0f;        // reset for next graph replay
            g_ticket = 0u;
        }
    }
}

extern "C" void kernel_launch(void* const* d_in, const int* in_sizes, int n_in,
                              void* d_out, int out_size) {
    const float* positions = (const float*)d_in[0];
    const float* euler     = (const float*)d_in[1];
    const float* coords    = (const float*)d_in[2];
    float* out = (float*)d_out;

    fused_kernel<<<TOTAL_BLOCKS, THREADS>>>(positions, euler, coords, out);
}

// round 12
// speedup vs baseline: 1.1577x; 1.1577x over previous
#include <cuda_runtime.h>
#include <cuda_bf16.h>

#define NU 8
#define MA 1024
#define NPAIRS 28               // NU*(NU-1)/2
#define JC 32                   // j chunks per unit
#define JT 32                   // j tile size
#define THREADS 256
#define NTILES (NPAIRS * JC)    // 896 tiles: 1024 i x 32 j each
#define PAIR_BLOCKS 592         // 4 blocks/SM x 148 SMs: one resident wave
#define TOTAL_BLOCKS (PAIR_BLOCKS + NU)

__device__ float g_acc;        // single accumulator; reset by finalizer
__device__ unsigned g_ticket;  // arrival counter; reset by finalizer

__device__ __forceinline__ unsigned long long pk2(float a, float b) {
    unsigned long long r;
    asm("mov.b64 %0, {%1, %2};" : "=l"(r) : "f"(a), "f"(b));
    return r;
}
__device__ __forceinline__ void upk2(float& a, float& b, unsigned long long v) {
    asm("mov.b64 {%0, %1}, %2;" : "=f"(a), "=f"(b) : "l"(v));
}
__device__ __forceinline__ unsigned long long fma2(unsigned long long a, unsigned long long b, unsigned long long c) {
    unsigned long long d;
    asm("fma.rn.f32x2 %0, %1, %2, %3;" : "=l"(d) : "l"(a), "l"(b), "l"(c));
    return d;
}
__device__ __forceinline__ float ex2f(float x) {
    float r;
    asm("ex2.approx.f32 %0, %1;" : "=r"(*(unsigned*)&r) : "r"(*(unsigned*)&x));
    return r;
}

// Build rotation matrices + positions into shared (threads 0..7, one unit each)
__device__ __forceinline__ void build_R(float (*Rsh)[12],
                                        const float* __restrict__ pos,
                                        const float* __restrict__ euler,
                                        int tid) {
    if (tid < NU) {
        float phi = euler[tid * 3 + 0];
        float the = euler[tid * 3 + 1];
        float psi = euler[tid * 3 + 2];
        float cp = __cosf(phi), sp = __sinf(phi);
        float ct = __cosf(the), st = __sinf(the);
        float cs = __cosf(psi), ss = __sinf(psi);
        // R = Rz(psi) @ Ry(theta) @ Rx(phi)
        Rsh[tid][0] = cs * ct;
        Rsh[tid][1] = -ss * cp + cs * st * sp;
        Rsh[tid][2] = ss * sp + cs * st * cp;
        Rsh[tid][3] = ss * ct;
        Rsh[tid][4] = cs * cp + ss * st * sp;
        Rsh[tid][5] = -cs * sp + ss * st * cp;
        Rsh[tid][6] = -st;
        Rsh[tid][7] = ct * sp;
        Rsh[tid][8] = ct * cp;
        Rsh[tid][9]  = pos[tid * 3 + 0];
        Rsh[tid][10] = pos[tid * 3 + 1];
        Rsh[tid][11] = pos[tid * 3 + 2];
    }
}

// Transform atom m with unit u's rotation+position (coords from global/L2)
__device__ __forceinline__ void xform(const float (*Rsh)[12],
                                      const float* __restrict__ coords,
                                      int u, int m,
                                      float& px, float& py, float& pz, float& sq) {
    float cx = coords[m * 3 + 0];
    float cy = coords[m * 3 + 1];
    float cz = coords[m * 3 + 2];
    const float* R = Rsh[u];
    px = fmaf(R[0], cx, fmaf(R[1], cy, fmaf(R[2], cz, R[9])));
    py = fmaf(R[3], cx, fmaf(R[4], cy, fmaf(R[5], cz, R[10])));
    pz = fmaf(R[6], cx, fmaf(R[7], cy, fmaf(R[8], cz, R[11])));
    sq = px * px + py * py + pz * pz;
}

// ---------------------------------------------------------------------------
// Single-wave persistent kernel.
// Blocks [0, 592): loop over tiles t = b, b+592 (tiles: pair = t>>5, jc = t&31;
//   each tile = full 1024 i (4/thread) x 32 j).
// Blocks [592, 600): L1 per unit (+ L_com in the first one).
// pen = exp2(c_i) * exp2(c_j + dot(Pi', Pj')),  P' = S*p, S^2 = 2*log2e,
// c = log2e*(0.5 - |p|^2)  =>  product = exp(1 - d2)
// ---------------------------------------------------------------------------
__global__ void __launch_bounds__(THREADS) fused_kernel(const float* __restrict__ pos,
                                                        const float* __restrict__ euler,
                                                        const float* __restrict__ coords,
                                                        float* __restrict__ out) {
    __shared__ float Rsh[NU][12];
    __shared__ __align__(16) float sj[4][JT];   // SoA j tile: X, Y, Z, c
    __shared__ float wsum[THREADS / 32];

    const float LOG2E = 1.4426950408889634f;
    const float S = 1.6986436005760381f;        // sqrt(2*log2e)
    int tid = threadIdx.x;
    int b = blockIdx.x;

    build_R(Rsh, pos, euler, tid);
    __syncthreads();

    float blockContrib = 0.0f;   // value thread 0 will atomicAdd

    if (b < PAIR_BLOCKS) {
        float acc = 0.0f;        // per-thread across tiles

        for (int t = b; t < NTILES; t += PAIR_BLOCKS) {
            int p  = t >> 5;          // pair index
            int jc = t & 31;          // j chunk
            // pair index -> (u, v), u < v
            int rem = p, u = 0, row = NU - 1;
            while (rem >= row) { rem -= row; row--; u++; }
            int v = u + 1 + rem;

            // Stage j tile (unit v); barrier protects smem reuse across tiles
            __syncthreads();
            if (tid < JT) {
                float px, py, pz, sq;
                xform(Rsh, coords, v, jc * JT + tid, px, py, pz, sq);
                sj[0][tid] = S * px;
                sj[1][tid] = S * py;
                sj[2][tid] = S * pz;
                sj[3][tid] = LOG2E * (0.5f - sq);
            }

            // i points (unit u): 4 per thread
            float px0, py0, pz0, sq0, px1, py1, pz1, sq1;
            float px2, py2, pz2, sq2, px3, py3, pz3, sq3;
            xform(Rsh, coords, u, tid,                px0, py0, pz0, sq0);
            xform(Rsh, coords, u, tid + THREADS,      px1, py1, pz1, sq1);
            xform(Rsh, coords, u, tid + 2 * THREADS,  px2, py2, pz2, sq2);
            xform(Rsh, coords, u, tid + 3 * THREADS,  px3, py3, pz3, sq3);

            unsigned long long DX0 = pk2(S * px0, S * px0), DY0 = pk2(S * py0, S * py0), DZ0 = pk2(S * pz0, S * pz0);
            unsigned long long DX1 = pk2(S * px1, S * px1), DY1 = pk2(S * py1, S * py1), DZ1 = pk2(S * pz1, S * pz1);
            unsigned long long DX2 = pk2(S * px2, S * px2), DY2 = pk2(S * py2, S * py2), DZ2 = pk2(S * pz2, S * pz2);
            unsigned long long DX3 = pk2(S * px3, S * px3), DY3 = pk2(S * py3, S * py3), DZ3 = pk2(S * pz3, S * pz3);
            float e0 = ex2f(LOG2E * (0.5f - sq0));
            float e1 = ex2f(LOG2E * (0.5f - sq1));
            float e2 = ex2f(LOG2E * (0.5f - sq2));
            float e3 = ex2f(LOG2E * (0.5f - sq3));

            __syncthreads();

            const unsigned long long* xp = reinterpret_cast<const unsigned long long*>(sj[0]);
            const unsigned long long* yp = reinterpret_cast<const unsigned long long*>(sj[1]);
            const unsigned long long* zp = reinterpret_cast<const unsigned long long*>(sj[2]);
            const unsigned long long* cp = reinterpret_cast<const unsigned long long*>(sj[3]);

            float s0 = 0.f, s1 = 0.f, s2 = 0.f, s3 = 0.f;

#pragma unroll
            for (int k = 0; k < JT / 2; k++) {
                unsigned long long XJ = xp[k];
                unsigned long long YJ = yp[k];
                unsigned long long ZJ = zp[k];
                unsigned long long CJ = cp[k];
                float lo, hi;

                unsigned long long t0 = fma2(DX0, XJ, CJ);
                t0 = fma2(DY0, YJ, t0);
                t0 = fma2(DZ0, ZJ, t0);
                upk2(lo, hi, t0);
                s0 += ex2f(lo);
                s0 += ex2f(hi);

                unsigned long long t1 = fma2(DX1, XJ, CJ);
                t1 = fma2(DY1, YJ, t1);
                t1 = fma2(DZ1, ZJ, t1);
                upk2(lo, hi, t1);
                s1 += ex2f(lo);
                s1 += ex2f(hi);

                unsigned long long t2 = fma2(DX2, XJ, CJ);
                t2 = fma2(DY2, YJ, t2);
                t2 = fma2(DZ2, ZJ, t2);
                upk2(lo, hi, t2);
                s2 += ex2f(lo);
                s2 += ex2f(hi);

                unsigned long long t3 = fma2(DX3, XJ, CJ);
                t3 = fma2(DY3, YJ, t3);
                t3 = fma2(DZ3, ZJ, t3);
                upk2(lo, hi, t3);
                s3 += ex2f(lo);
                s3 += ex2f(hi);
            }

            acc += fmaf(e0, s0, fmaf(e1, s1, fmaf(e2, s2, e3 * s3)));
        }

        // block reduce
        float s = acc;
#pragma unroll
        for (int o = 16; o > 0; o >>= 1)
            s += __shfl_xor_sync(0xFFFFFFFFu, s, o);
        if ((tid & 31) == 0) wsum[tid >> 5] = s;
        __syncthreads();
        if (tid == 0) {
            float bs = 0.f;
#pragma unroll
            for (int w = 0; w < THREADS / 32; w++) bs += wsum[w];
            blockContrib = 0.5f * bs;      // LAMBDA1 = 0.5
        }
    } else {
        // L1 block for unit u (+ L_com in the u==0 block)
        int u = b - PAIR_BLOCKS;
        float l1 = 0.0f;
#pragma unroll
        for (int k = 0; k < MA / THREADS; k++) {
            float px, py, pz, sq;
            xform(Rsh, coords, u, k * THREADS + tid, px, py, pz, sq);
            l1 += sq;
        }
#pragma unroll
        for (int o = 16; o > 0; o >>= 1)
            l1 += __shfl_xor_sync(0xFFFFFFFFu, l1, o);
        if ((tid & 31) == 0) wsum[tid >> 5] = l1;
        __syncthreads();
        if (tid == 0) {
            float bs = 0.f;
#pragma unroll
            for (int w = 0; w < THREADS / 32; w++) bs += wsum[w];
            blockContrib = bs / (float)NU;      // contribution to L1 mean
            if (u == 0) {
                float ccx = 0.f, ccy = 0.f, ccz = 0.f;
#pragma unroll
                for (int uu = 0; uu < NU; uu++) {
                    ccx += Rsh[uu][9]; ccy += Rsh[uu][10]; ccz += Rsh[uu][11];
                }
                blockContrib += ccx * ccx + ccy * ccy + ccz * ccz;   // ALPHA = 1
            }
        }
    }

    // Accumulate + ticket finalize (thread 0 of every block)
    if (tid == 0) {
        atomicAdd(&g_acc, blockContrib);
        __threadfence();
        unsigned old = atomicAdd(&g_ticket, 1u);
        if (old == TOTAL_BLOCKS - 1) {
            __threadfence();
            float total = *((volatile float*)&g_acc);
            out[0] = total;
            g_acc = 0.0f;        // reset for next graph replay
            g_ticket = 0u;
        }
    }
}

extern "C" void kernel_launch(void* const* d_in, const int* in_sizes, int n_in,
                              void* d_out, int out_size) {
    const float* positions = (const float*)d_in[0];
    const float* euler     = (const float*)d_in[1];
    const float* coords    = (const float*)d_in[2];
    float* out = (float*)d_out;

    fused_kernel<<<TOTAL_BLOCKS, THREADS>>>(positions, euler, coords, out);
}